// round 3
// baseline (speedup 1.0000x reference)
#include <cuda_runtime.h>
#include <math.h>

#define N_REGS 32
#define KEY_DIM 128
#define BIT_WIDTH 64
#define TAB_VEC4 (N_REGS * BIT_WIDTH / 4)   // 512
#define NBUILD 8
#define THREADS 256
#define GRID 1184
#define UNROLL 4

// Precomputed output table: one 64-float row per idx value. 8 KB.
__device__ float g_table[N_REGS * BIT_WIDTH];
// Producer/consumer handshake flags (self-resetting each launch).
__device__ unsigned g_ready = 0;
__device__ unsigned g_done  = 0;

__device__ __forceinline__ float gelu_exact(float x) {
    // 0.5 * x * (1 + erf(x / sqrt(2)))  — matches jax.nn.gelu(approximate=False)
    return 0.5f * x * (1.0f + erff(x * 0.70710678118654752440f));
}

__global__ void __launch_bounds__(THREADS, 8) fused_kernel(
    const int*   __restrict__ idx,
    const float* __restrict__ W1,          // [5, 128]
    const float* __restrict__ b1,          // [128]
    const float* __restrict__ W2,          // [128, 128]
    const float* __restrict__ b2,          // [128]
    const float* __restrict__ keys,        // [32, 128]
    const float* __restrict__ temperature, // scalar
    const float* __restrict__ rv,          // [32, 64]
    float4*      __restrict__ out,
    int total_vec4)                        // = B * 16
{
    __shared__ float4 stab[TAB_VEC4];      // 8 KB staged table

    const int tid = threadIdx.x;

    // ---------------- Producer phase: blocks 0..7 build 4 table rows each ----
    if (blockIdx.x < NBUILD) {
        __shared__ float sh_h[2][KEY_DIM];
        __shared__ float sh_q[2][KEY_DIM];
        __shared__ float sh_a[2][N_REGS];

        const int which = tid >> 7;        // 0 or 1: which idx of the pair
        const int col   = tid & 127;

        #pragma unroll
        for (int it = 0; it < 2; it++) {
            const int idv = (int)blockIdx.x * 4 + it * 2 + which;

            // h = gelu(bits @ W1 + b1)
            {
                float acc = b1[col];
                #pragma unroll
                for (int k = 0; k < 5; k++)
                    if ((idv >> k) & 1) acc += W1[k * KEY_DIM + col];
                sh_h[which][col] = gelu_exact(acc);
            }
            __syncthreads();

            // query = h @ W2 + b2 (both halves read the same W2 -> L1 hits)
            {
                float q = b2[col];
                #pragma unroll 8
                for (int j = 0; j < KEY_DIM; j++)
                    q = fmaf(sh_h[which][j], W2[j * KEY_DIM + col], q);
                sh_q[which][col] = q;
            }
            __syncthreads();

            // sim[r] = q . keys[r], 4 lanes per register row
            {
                int r = col >> 2, part = col & 3;
                float s = 0.0f;
                #pragma unroll 8
                for (int i = part * 32; i < part * 32 + 32; i++)
                    s = fmaf(sh_q[which][i], keys[r * KEY_DIM + i], s);
                s += __shfl_xor_sync(0xffffffffu, s, 1);
                s += __shfl_xor_sync(0xffffffffu, s, 2);
                if (part == 0) sh_a[which][r] = s;
            }
            __syncthreads();

            // softmax over 32 (warp 0 for which=0, warp 4 for which=1)
            if (col < N_REGS) {
                float temp = fmaxf(fabsf(temperature[0]), 0.1f);
                float s = sh_a[which][col] / temp;
                float m = s;
                #pragma unroll
                for (int off = 16; off > 0; off >>= 1)
                    m = fmaxf(m, __shfl_xor_sync(0xffffffffu, m, off));
                float e = expf(s - m);
                float sum = e;
                #pragma unroll
                for (int off = 16; off > 0; off >>= 1)
                    sum += __shfl_xor_sync(0xffffffffu, sum, off);
                sh_a[which][col] = e / sum;
            }
            __syncthreads();

            // table row = attn @ register_values; XZR (idx==31) forced to zero
            if (col < BIT_WIDTH) {
                float v = 0.0f;
                #pragma unroll
                for (int r = 0; r < N_REGS; r++)
                    v = fmaf(sh_a[which][r], rv[r * BIT_WIDTH + col], v);
                if (idv == 31) v = 0.0f;
                g_table[idv * BIT_WIDTH + col] = v;
            }
            __syncthreads();
        }
        __threadfence();
        if (tid == 0) atomicAdd(&g_ready, 1u);
    }

    // ---------------- Handshake: wait until all 32 table rows are published --
    if (tid == 0) {
        while (atomicAdd(&g_ready, 0u) < NBUILD) __nanosleep(64);
    }
    __syncthreads();

    // Stage table into smem. __ldcg bypasses L1 -> coherent with builders' L2 data.
    const float4* gt = reinterpret_cast<const float4*>(g_table);
    for (int i = tid; i < TAB_VEC4; i += THREADS)
        stab[i] = __ldcg(&gt[i]);
    __syncthreads();

    // ---------------- Consumer phase: persistent grid-stride gather ----------
    // Thread element stride = GRID*THREADS (0 mod 16) so c = t & 15 is constant:
    // stores stay fully coalesced, smem reads conflict-free.
    const int step = GRID * THREADS;
    int base = (int)blockIdx.x * THREADS + tid;

    for (; base + (UNROLL - 1) * step < total_vec4; base += UNROLL * step) {
        int r[UNROLL];
        #pragma unroll
        for (int u = 0; u < UNROLL; u++)
            r[u] = __ldcs(&idx[(base + u * step) >> 4]);   // MLP=UNROLL
        float4 v[UNROLL];
        #pragma unroll
        for (int u = 0; u < UNROLL; u++)
            v[u] = stab[(r[u] << 4) + ((base + u * step) & 15)];
        #pragma unroll
        for (int u = 0; u < UNROLL; u++)
            __stcs(&out[base + u * step], v[u]);           // streaming store
    }
    for (; base < total_vec4; base += step) {
        int rr = __ldcs(&idx[base >> 4]);
        __stcs(&out[base], stab[(rr << 4) + (base & 15)]);
    }

    // ---------------- Reset flags for the next graph replay ------------------
    __syncthreads();
    if (tid == 0) {
        unsigned old = atomicAdd(&g_done, 1u);
        if (old == gridDim.x - 1) {
            atomicExch(&g_ready, 0u);
            atomicExch(&g_done, 0u);
        }
    }
}

extern "C" void kernel_launch(void* const* d_in, const int* in_sizes, int n_in,
                              void* d_out, int out_size)
{
    const int*   idx  = (const int*)  d_in[0];
    const float* W1   = (const float*)d_in[1];
    const float* b1   = (const float*)d_in[2];
    const float* W2   = (const float*)d_in[3];
    const float* b2   = (const float*)d_in[4];
    const float* keys = (const float*)d_in[5];
    const float* temp = (const float*)d_in[6];
    const float* rv   = (const float*)d_in[7];

    const int B = in_sizes[0];
    const int total_vec4 = B * (BIT_WIDTH / 4);   // B * 16

    fused_kernel<<<GRID, THREADS>>>(idx, W1, b1, W2, b2, keys, temp, rv,
                                    (float4*)d_out, total_vec4);
}

// round 4
// speedup vs baseline: 1.1720x; 1.1720x over previous
#include <cuda_runtime.h>
#include <math.h>

#define N_REGS 32
#define KEY_DIM 128
#define BIT_WIDTH 64
#define TAB_VEC4 (N_REGS * BIT_WIDTH / 4)   // 512
#define THREADS 256
#define GRID 1184                            // 148 SMs * 8 CTAs = one full wave
#define UNROLL 4

// Precomputed output table: one 64-float row per idx value. 8 KB.
__device__ float g_table[N_REGS * BIT_WIDTH];
// Handshake (self-resetting each launch).
__device__ unsigned g_ready = 0;   // builder completion counter (32 atomics total)
__device__ unsigned g_go    = 0;   // single release flag, polled with plain loads
__device__ unsigned g_done  = 0;   // reset coordination

__device__ __forceinline__ float gelu_exact(float x) {
    // 0.5 * x * (1 + erf(x / sqrt(2)))  — matches jax.nn.gelu(approximate=False)
    return 0.5f * x * (1.0f + erff(x * 0.70710678118654752440f));
}

__global__ void __launch_bounds__(THREADS, 8) fused_kernel(
    const int*   __restrict__ idx,
    const float* __restrict__ W1,          // [5, 128]
    const float* __restrict__ b1,          // [128]
    const float* __restrict__ W2,          // [128, 128]
    const float* __restrict__ b2,          // [128]
    const float* __restrict__ keys,        // [32, 128]
    const float* __restrict__ temperature, // scalar
    const float* __restrict__ rv,          // [32, 64]
    float4*      __restrict__ out,
    int total_vec4)                        // = B * 16
{
    __shared__ float4 stab[TAB_VEC4];      // 8 KB staged table

    const int tid = threadIdx.x;

    // ------------- Producer phase: blocks 0..31 build one table row each ----
    if (blockIdx.x < N_REGS) {
        __shared__ float sh_h[KEY_DIM];
        __shared__ float sh_q[KEY_DIM];
        __shared__ float sh_a[N_REGS];

        const int idv = (int)blockIdx.x;

        // h = gelu(bits @ W1 + b1)
        if (tid < KEY_DIM) {
            float acc = b1[tid];
            #pragma unroll
            for (int k = 0; k < 5; k++)
                if ((idv >> k) & 1) acc += W1[k * KEY_DIM + tid];
            sh_h[tid] = gelu_exact(acc);
        }
        __syncthreads();

        // query = h @ W2 + b2 (coalesced across tid; unroll 8 -> MLP 8)
        if (tid < KEY_DIM) {
            float q = b2[tid];
            #pragma unroll 8
            for (int j = 0; j < KEY_DIM; j++)
                q = fmaf(sh_h[j], W2[j * KEY_DIM + tid], q);
            sh_q[tid] = q;
        }
        __syncthreads();

        // sim[r] = q . keys[r], 4 lanes per register row (threads 0..127)
        if (tid < 128) {
            int r = tid >> 2, part = tid & 3;
            float s = 0.0f;
            #pragma unroll 8
            for (int i = part * 32; i < part * 32 + 32; i++)
                s = fmaf(sh_q[i], keys[r * KEY_DIM + i], s);
            s += __shfl_xor_sync(0xffffffffu, s, 1);
            s += __shfl_xor_sync(0xffffffffu, s, 2);
            if (part == 0) sh_a[r] = s;
        }
        __syncthreads();

        // softmax over 32 (warp 0)
        if (tid < N_REGS) {
            float temp = fmaxf(fabsf(temperature[0]), 0.1f);
            float s = sh_a[tid] / temp;
            float m = s;
            #pragma unroll
            for (int off = 16; off > 0; off >>= 1)
                m = fmaxf(m, __shfl_xor_sync(0xffffffffu, m, off));
            float e = expf(s - m);
            float sum = e;
            #pragma unroll
            for (int off = 16; off > 0; off >>= 1)
                sum += __shfl_xor_sync(0xffffffffu, sum, off);
            sh_a[tid] = e / sum;
        }
        __syncthreads();

        // table row = attn @ register_values; XZR (idx==31) forced to zero
        if (tid < BIT_WIDTH) {
            float v = 0.0f;
            #pragma unroll
            for (int r = 0; r < N_REGS; r++)
                v = fmaf(sh_a[r], rv[r * BIT_WIDTH + tid], v);
            if (idv == 31) v = 0.0f;
            g_table[idv * BIT_WIDTH + tid] = v;
        }
        __syncthreads();
        __threadfence();                      // publish table row to L2
        if (tid == 0) {
            unsigned prev = atomicAdd(&g_ready, 1u);
            if (prev == N_REGS - 1) {
                __threadfence();
                atomicExch(&g_go, 1u);        // release: all 32 rows visible
            }
        }
    }

    // ------------- Handshake: plain-load poll (NO atomic RMW) ----------------
    if (tid == 0) {
        while (*(volatile unsigned*)&g_go == 0u) __nanosleep(128);
    }
    __syncthreads();

    // Stage table into smem. __ldcg bypasses L1 -> coherent with builders' L2 data.
    const float4* gt = reinterpret_cast<const float4*>(g_table);
    for (int i = tid; i < TAB_VEC4; i += THREADS)
        stab[i] = __ldcg(&gt[i]);
    __syncthreads();

    // ------------- Consumer phase: persistent grid-stride gather -------------
    // Thread element stride = GRID*THREADS (0 mod 16) so c = t & 15 is constant:
    // stores stay fully coalesced, smem reads conflict-free.
    const int step = GRID * THREADS;
    int base = (int)blockIdx.x * THREADS + tid;

    for (; base + (UNROLL - 1) * step < total_vec4; base += UNROLL * step) {
        int r[UNROLL];
        #pragma unroll
        for (int u = 0; u < UNROLL; u++)
            r[u] = __ldcs(&idx[(base + u * step) >> 4]);   // MLP=UNROLL
        float4 v[UNROLL];
        #pragma unroll
        for (int u = 0; u < UNROLL; u++)
            v[u] = stab[(r[u] << 4) + ((base + u * step) & 15)];
        #pragma unroll
        for (int u = 0; u < UNROLL; u++)
            __stcs(&out[base + u * step], v[u]);           // streaming store
    }
    for (; base < total_vec4; base += step) {
        int rr = __ldcs(&idx[base >> 4]);
        __stcs(&out[base], stab[(rr << 4) + (base & 15)]);
    }

    // ------------- Reset flags for the next graph replay ---------------------
    __syncthreads();
    if (tid == 0) {
        unsigned old = atomicAdd(&g_done, 1u);
        if (old == (unsigned)(gridDim.x - 1)) {
            atomicExch(&g_ready, 0u);
            atomicExch(&g_go, 0u);
            atomicExch(&g_done, 0u);
        }
    }
}

extern "C" void kernel_launch(void* const* d_in, const int* in_sizes, int n_in,
                              void* d_out, int out_size)
{
    const int*   idx  = (const int*)  d_in[0];
    const float* W1   = (const float*)d_in[1];
    const float* b1   = (const float*)d_in[2];
    const float* W2   = (const float*)d_in[3];
    const float* b2   = (const float*)d_in[4];
    const float* keys = (const float*)d_in[5];
    const float* temp = (const float*)d_in[6];
    const float* rv   = (const float*)d_in[7];

    const int B = in_sizes[0];
    const int total_vec4 = B * (BIT_WIDTH / 4);   // B * 16

    fused_kernel<<<GRID, THREADS>>>(idx, W1, b1, W2, b2, keys, temp, rv,
                                    (float4*)d_out, total_vec4);
}